// round 15
// baseline (speedup 1.0000x reference)
#include <cuda_runtime.h>
#include <math.h>

#define HH 512
#define WW 512
#define NB 64
#define PD 15
#define RB 32                 // rows per band (per CTA)
#define BANDS (HH / RB)       // 16
#define GG 8                  // rows per smem group
#define NGROUPS (RB / GG)     // 4
#define NTH 256
#define SBW 560               // swizzled row width
#define NBLOCKS (BANDS * NB)  // 1024

__device__ __forceinline__ int scol(int c) { return c + (c >> 5); }

// sigmoid(x) = 0.5 * (1 + tanh(x/2)) using HW tanh.approx (sm_75+)
__device__ __forceinline__ float fast_sigmoid(float x) {
    float th;
    asm("tanh.approx.f32 %0, %1;" : "=f"(th) : "f"(0.5f * x));
    return fmaf(0.5f, th, 0.5f);
}

__device__ float g_part[NB * BANDS * 2];
__device__ unsigned int g_count = 0;

__global__ __launch_bounds__(NTH, 6)
void fused_kernel(const float* __restrict__ pred, const float* __restrict__ mask,
                  float* __restrict__ out) {
    __shared__ float buf[2][GG][SBW];       // 35,840 B
    __shared__ float s_i[8], s_u[8];
    __shared__ bool amLast;

    const int t    = threadIdx.x;           // owns column pair (2t, 2t+1) in phase A
    const int band = blockIdx.x;
    const int b    = blockIdx.y;
    const int r0   = band * RB;
    const float*  mb  = mask + (size_t)b * HH * WW;
    const float*  pb  = pred + (size_t)b * HH * WW;
    const float2* mb2 = reinterpret_cast<const float2*>(mb);
    const int ca = 2 * t;                   // phase-A base column

    // zero both buffers once (halo regions stay zero thereafter)
    #pragma unroll
    for (int i = t; i < 2 * GG * SBW; i += NTH) ((float*)buf)[i] = 0.f;

    // vertical running-sum init: 30 rows [r0-15, r0+14], float2, 4-way ILP tree
    float s0, s1;
    {
        float2 a0 = {0.f, 0.f}, a1 = {0.f, 0.f}, a2 = {0.f, 0.f}, a3 = {0.f, 0.f};
        #pragma unroll
        for (int j = 0; j < 28; j += 4) {
            int g0 = r0 - PD + j;
            if (g0 + 0 >= 0) { float2 v = mb2[(g0 + 0) * (WW/2) + t]; a0.x += v.x; a0.y += v.y; }
            if (g0 + 1 >= 0) { float2 v = mb2[(g0 + 1) * (WW/2) + t]; a1.x += v.x; a1.y += v.y; }
            if (g0 + 2 >= 0) { float2 v = mb2[(g0 + 2) * (WW/2) + t]; a2.x += v.x; a2.y += v.y; }
            if (g0 + 3 >= 0) { float2 v = mb2[(g0 + 3) * (WW/2) + t]; a3.x += v.x; a3.y += v.y; }
        }
        int g28 = r0 - PD + 28, g29 = r0 - PD + 29;
        if (g28 >= 0) { float2 v = mb2[g28 * (WW/2) + t]; a0.x += v.x; a0.y += v.y; }
        if (g29 >= 0) { float2 v = mb2[g29 * (WW/2) + t]; a1.x += v.x; a1.y += v.y; }
        s0 = (a0.x + a1.x) + (a2.x + a3.x);
        s1 = (a0.y + a1.y) + (a2.y + a3.y);
    }

    // zeroing must complete before any staged interior write
    __syncthreads();

    // ---- prologue: phase A for group 0 into buf[0] ----
    #pragma unroll
    for (int rr = 0; rr < GG; ++rr) {
        int gr = r0 + rr;
        float2 lead = (gr + PD < HH) ? mb2[(gr + PD) * (WW/2) + t] : make_float2(0.f, 0.f);
        s0 += lead.x; s1 += lead.y;
        buf[0][rr][scol(ca + PD)]     = s0;
        buf[0][rr][scol(ca + PD + 1)] = s1;
        float2 trail = (gr - PD >= 0) ? mb2[(gr - PD) * (WW/2) + t] : make_float2(0.f, 0.f);
        s0 -= trail.x; s1 -= trail.y;
    }
    __syncthreads();

    const float inv = 1.0f / 961.0f;
    float fi = 0.f, fu = 0.f;

    // phase-B mapping: 64 threads per row-sweep, 8 cols per thread, 2 sweeps
    const int rg   = t >> 6;                // 0..3 base row-in-group
    const int c0   = (t & 63) * 8;          // 8-chunk base (buffer idx)
    const int lane = t & 31;

    for (int g = 0; g < NGROUPS; ++g) {
        // ---- phase A for group g+1 into buf[(g+1)&1] (overlaps phase B) ----
        if (g + 1 < NGROUPS) {
            const int rbase = r0 + (g + 1) * GG;
            float* bw = &buf[(g + 1) & 1][0][0];
            #pragma unroll
            for (int rr = 0; rr < GG; ++rr) {
                int gr = rbase + rr;
                float2 lead = (gr + PD < HH) ? mb2[(gr + PD) * (WW/2) + t] : make_float2(0.f, 0.f);
                s0 += lead.x; s1 += lead.y;
                bw[rr * SBW + scol(ca + PD)]     = s0;
                bw[rr * SBW + scol(ca + PD + 1)] = s1;
                float2 trail = (gr - PD >= 0) ? mb2[(gr - PD) * (WW/2) + t] : make_float2(0.f, 0.f);
                s0 -= trail.x; s1 -= trail.y;
            }
        }

        // ---- phase B for group g from buf[g&1]: two row sweeps ----
        #pragma unroll
        for (int sw = 0; sw < 2; ++sw) {
            const int rrow = rg + 4 * sw;                  // 0..7
            const int grB  = r0 + g * GG + rrow;
            const float* br   = &buf[g & 1][rrow][0];
            const float* mrow = mb + grB * WW + c0;
            const float* prow = pb + grB * WW + c0;

            // own chunk: buffer idx [c0, c0+7] (also the slide-subtract values)
            float o0 = br[scol(c0 + 0)], o1 = br[scol(c0 + 1)];
            float o2 = br[scol(c0 + 2)], o3 = br[scol(c0 + 3)];
            float o4 = br[scol(c0 + 4)], o5 = br[scol(c0 + 5)];
            float o6 = br[scol(c0 + 6)], o7 = br[scol(c0 + 7)];
            float S = ((o0 + o1) + (o2 + o3)) + ((o4 + o5) + (o6 + o7));
            float U = S - o7;

            // window init = idx [c0, c0+30] = S_l + S_{l+1} + S_{l+2} + U_{l+3}
            float s1f = __shfl_down_sync(0xffffffffu, S, 1);
            float s2f = __shfl_down_sync(0xffffffffu, S, 2);
            float u3f = __shfl_down_sync(0xffffffffu, U, 3);
            float hs = S + s1f + s2f + u3f;

            // lanes 29..31: neighbor chunks cross the warp edge -> direct LDS
            if (lane >= 29) {
                float a0 = 0.f, a1 = 0.f, a2 = 0.f, a3 = 0.f;
                #pragma unroll
                for (int j = 8; j < 28; j += 4) {
                    a0 += br[scol(c0 + j + 0)];
                    a1 += br[scol(c0 + j + 1)];
                    a2 += br[scol(c0 + j + 2)];
                    a3 += br[scol(c0 + j + 3)];
                }
                a0 += br[scol(c0 + 28)];
                a1 += br[scol(c0 + 29)];
                a2 += br[scol(c0 + 30)];
                hs = S + (a0 + a1) + (a2 + a3);
            }

            float own[8] = {o0, o1, o2, o3, o4, o5, o6, o7};

            // two 4-column register batches; subtract side from cached regs
            #pragma unroll
            for (int h = 0; h < 2; ++h) {
                float4 m4 = *reinterpret_cast<const float4*>(mrow + h * 4);
                float4 p4 = *reinterpret_cast<const float4*>(prow + h * 4);
                float mk[4] = {m4.x, m4.y, m4.z, m4.w};
                float pr[4] = {p4.x, p4.y, p4.z, p4.w};
                #pragma unroll
                for (int q = 0; q < 4; ++q) {
                    int c = c0 + h * 4 + q;
                    float avg  = hs * inv;
                    float weit = fmaf(5.f, fabsf(avg - mk[q]), 1.f);
                    float p    = fast_sigmoid(pr[q]);
                    fi = fmaf(p * mk[q], weit, fi);
                    fu = fmaf(p + mk[q], weit, fu);
                    hs += br[scol(c + 31)] - own[h * 4 + q];
                }
            }
        }
        __syncthreads();
    }

    // ---- block reduce 256 -> 1 ----
    #pragma unroll
    for (int o = 16; o; o >>= 1) {
        fi += __shfl_down_sync(0xffffffffu, fi, o);
        fu += __shfl_down_sync(0xffffffffu, fu, o);
    }
    int wid = t >> 5;
    if (lane == 0) { s_i[wid] = fi; s_u[wid] = fu; }
    __syncthreads();
    if (wid == 0) {
        float ti = (lane < 8) ? s_i[lane] : 0.f;
        float tu = (lane < 8) ? s_u[lane] : 0.f;
        #pragma unroll
        for (int o = 4; o; o >>= 1) {
            ti += __shfl_down_sync(0xffffffffu, ti, o);
            tu += __shfl_down_sync(0xffffffffu, tu, o);
        }
        if (lane == 0) {
            g_part[(b * BANDS + band) * 2 + 0] = ti;
            g_part[(b * BANDS + band) * 2 + 1] = tu;
            __threadfence();
            unsigned int done = atomicAdd(&g_count, 1u);
            amLast = (done == NBLOCKS - 1);
        }
    }
    __syncthreads();

    // ---- last CTA: finalize ----
    if (amLast) {
        double w = 0.0;
        if (t < NB) {
            double it = 0.0, un = 0.0;
            #pragma unroll
            for (int p = 0; p < BANDS; ++p) {
                it += (double)g_part[(t * BANDS + p) * 2 + 0];
                un += (double)g_part[(t * BANDS + p) * 2 + 1];
            }
            w = 1.0 - (2.0 * it + 0.5) / (un + 0.5);
        }
        #pragma unroll
        for (int o = 16; o; o >>= 1) w += __shfl_down_sync(0xffffffffu, w, o);
        __shared__ double sh[2];
        if (t < 64 && (t & 31) == 0) sh[t >> 5] = w;
        __syncthreads();
        if (t == 0) {
            out[0] = (float)((sh[0] + sh[1]) / (double)NB);
            g_count = 0;   // reset for next graph replay
        }
    }
}

extern "C" void kernel_launch(void* const* d_in, const int* in_sizes, int n_in,
                              void* d_out, int out_size) {
    const float* pred = (const float*)d_in[0];
    const float* mask = (const float*)d_in[1];
    float* out = (float*)d_out;

    fused_kernel<<<dim3(BANDS, NB), NTH>>>(pred, mask, out);
}

// round 16
// speedup vs baseline: 1.2565x; 1.2565x over previous
#include <cuda_runtime.h>
#include <math.h>

#define HH 512
#define WW 512
#define NB 64
#define PD 15
#define RB 32                 // rows per band (per CTA)
#define BANDS (HH / RB)       // 16
#define GG 4                  // rows per smem group
#define NGROUPS (RB / GG)     // 8
#define NTH 128
#define SBW 560               // swizzled row width
#define NBLOCKS (BANDS * NB)  // 1024

__device__ __forceinline__ int scol(int c) { return c + (c >> 5); }

// sigmoid(x) = 0.5 * (1 + tanh(x/2)) using HW tanh.approx
__device__ __forceinline__ float fast_sigmoid(float x) {
    float th;
    asm("tanh.approx.f32 %0, %1;" : "=f"(th) : "f"(0.5f * x));
    return fmaf(0.5f, th, 0.5f);
}

__device__ float g_part[NB * BANDS * 2];
__device__ unsigned int g_count = 0;

__global__ __launch_bounds__(NTH, 10)
void fused_kernel(const float* __restrict__ pred, const float* __restrict__ mask,
                  float* __restrict__ out) {
    __shared__ float buf[2][GG][SBW];       // 17,920 B
    __shared__ float s_i[4], s_u[4];
    __shared__ bool amLast;

    const int t    = threadIdx.x;
    const int band = blockIdx.x;
    const int b    = blockIdx.y;
    const int r0   = band * RB;
    const float*  mb  = mask + (size_t)b * HH * WW;
    const float*  pb  = pred + (size_t)b * HH * WW;
    const float4* mb4 = reinterpret_cast<const float4*>(mb);
    const int ca = 4 * t;                   // phase-A base column (4 cols/thread)

    // zero both buffers once (halo regions stay zero thereafter)
    #pragma unroll
    for (int i = t; i < 2 * GG * SBW; i += NTH) ((float*)buf)[i] = 0.f;

    // vertical running-sum init: 30 rows [r0-15, r0+14], float4, 4-way ILP tree
    float4 s;
    {
        float4 a0 = {0,0,0,0}, a1 = {0,0,0,0}, a2 = {0,0,0,0}, a3 = {0,0,0,0};
        #pragma unroll
        for (int j = 0; j < 28; j += 4) {
            int g0 = r0 - PD + j;
            if (g0 + 0 >= 0) { float4 v = mb4[(g0 + 0) * (WW/4) + t]; a0.x += v.x; a0.y += v.y; a0.z += v.z; a0.w += v.w; }
            if (g0 + 1 >= 0) { float4 v = mb4[(g0 + 1) * (WW/4) + t]; a1.x += v.x; a1.y += v.y; a1.z += v.z; a1.w += v.w; }
            if (g0 + 2 >= 0) { float4 v = mb4[(g0 + 2) * (WW/4) + t]; a2.x += v.x; a2.y += v.y; a2.z += v.z; a2.w += v.w; }
            if (g0 + 3 >= 0) { float4 v = mb4[(g0 + 3) * (WW/4) + t]; a3.x += v.x; a3.y += v.y; a3.z += v.z; a3.w += v.w; }
        }
        int g28 = r0 - PD + 28, g29 = r0 - PD + 29;
        if (g28 >= 0) { float4 v = mb4[g28 * (WW/4) + t]; a0.x += v.x; a0.y += v.y; a0.z += v.z; a0.w += v.w; }
        if (g29 >= 0) { float4 v = mb4[g29 * (WW/4) + t]; a1.x += v.x; a1.y += v.y; a1.z += v.z; a1.w += v.w; }
        s.x = (a0.x + a1.x) + (a2.x + a3.x);
        s.y = (a0.y + a1.y) + (a2.y + a3.y);
        s.z = (a0.z + a1.z) + (a2.z + a3.z);
        s.w = (a0.w + a1.w) + (a2.w + a3.w);
    }

    __syncthreads();   // zeroing complete before staged interior writes

    // ---- prologue: phase A for group 0 into buf[0] ----
    #pragma unroll
    for (int rr = 0; rr < GG; ++rr) {
        int gr = r0 + rr;
        float4 lead = (gr + PD < HH) ? mb4[(gr + PD) * (WW/4) + t] : make_float4(0,0,0,0);
        s.x += lead.x; s.y += lead.y; s.z += lead.z; s.w += lead.w;
        buf[0][rr][scol(ca + PD + 0)] = s.x;
        buf[0][rr][scol(ca + PD + 1)] = s.y;
        buf[0][rr][scol(ca + PD + 2)] = s.z;
        buf[0][rr][scol(ca + PD + 3)] = s.w;
        float4 trail = (gr - PD >= 0) ? mb4[(gr - PD) * (WW/4) + t] : make_float4(0,0,0,0);
        s.x -= trail.x; s.y -= trail.y; s.z -= trail.z; s.w -= trail.w;
    }
    __syncthreads();

    const float inv = 1.0f / 961.0f;
    float fi = 0.f, fu = 0.f;

    // phase-B mapping: 32 lanes per row, 16 cols per lane
    const int rg   = t >> 5;                // 0..3 row-in-group (warp per row)
    const int lane = t & 31;
    const int c0   = lane * 16;

    for (int g = 0; g < NGROUPS; ++g) {
        // ---- phase A for group g+1 into buf[(g+1)&1] (overlaps phase B) ----
        if (g + 1 < NGROUPS) {
            const int rbase = r0 + (g + 1) * GG;
            float* bw = &buf[(g + 1) & 1][0][0];
            #pragma unroll
            for (int rr = 0; rr < GG; ++rr) {
                int gr = rbase + rr;
                float4 lead = (gr + PD < HH) ? mb4[(gr + PD) * (WW/4) + t] : make_float4(0,0,0,0);
                s.x += lead.x; s.y += lead.y; s.z += lead.z; s.w += lead.w;
                bw[rr * SBW + scol(ca + PD + 0)] = s.x;
                bw[rr * SBW + scol(ca + PD + 1)] = s.y;
                bw[rr * SBW + scol(ca + PD + 2)] = s.z;
                bw[rr * SBW + scol(ca + PD + 3)] = s.w;
                float4 trail = (gr - PD >= 0) ? mb4[(gr - PD) * (WW/4) + t] : make_float4(0,0,0,0);
                s.x -= trail.x; s.y -= trail.y; s.z -= trail.z; s.w -= trail.w;
            }
        }

        // ---- phase B for group g from buf[g&1] ----
        {
            const int grB = r0 + g * GG + rg;
            const float* br   = &buf[g & 1][rg][0];
            const float* mrow = mb + grB * WW + c0;
            const float* prow = pb + grB * WW + c0;

            // own chunk: buffer idx [c0, c0+15] (conflict-free scalar LDS)
            float own[16];
            #pragma unroll
            for (int j = 0; j < 16; ++j) own[j] = br[scol(c0 + j)];

            // chunk sum, ILP tree
            float S;
            {
                float a0 = (own[0] + own[1]) + (own[2] + own[3]);
                float a1 = (own[4] + own[5]) + (own[6] + own[7]);
                float a2 = (own[8] + own[9]) + (own[10] + own[11]);
                float a3 = (own[12] + own[13]) + (own[14] + own[15]);
                S = (a0 + a1) + (a2 + a3);
            }

            // window init = idx [c0, c0+30] = S + S_next - v[c0+31]
            float nS  = __shfl_down_sync(0xffffffffu, S, 1);
            float n15 = __shfl_down_sync(0xffffffffu, own[15], 1);
            float hs  = S + nS - n15;
            if (lane == 31) {
                // next chunk is idx [512..527]: 512..526 interior, 527 halo zero
                float a0 = 0.f, a1 = 0.f, a2 = 0.f, a3 = 0.f;
                #pragma unroll
                for (int j = 16; j < 28; j += 4) {
                    a0 += br[scol(c0 + j + 0)];
                    a1 += br[scol(c0 + j + 1)];
                    a2 += br[scol(c0 + j + 2)];
                    a3 += br[scol(c0 + j + 3)];
                }
                a0 += br[scol(c0 + 28)];
                a1 += br[scol(c0 + 29)];
                a2 += br[scol(c0 + 30)];
                hs = S + (a0 + a1) + (a2 + a3);
            }

            // four 4-column register batches; subtract side from cached regs
            #pragma unroll
            for (int h = 0; h < 4; ++h) {
                float4 m4 = *reinterpret_cast<const float4*>(mrow + h * 4);
                float4 p4 = *reinterpret_cast<const float4*>(prow + h * 4);
                float mk[4] = {m4.x, m4.y, m4.z, m4.w};
                float pr[4] = {p4.x, p4.y, p4.z, p4.w};
                #pragma unroll
                for (int q = 0; q < 4; ++q) {
                    int c = c0 + h * 4 + q;
                    float avg  = hs * inv;
                    float weit = fmaf(5.f, fabsf(avg - mk[q]), 1.f);
                    float p    = fast_sigmoid(pr[q]);
                    fi = fmaf(p * mk[q], weit, fi);
                    fu = fmaf(p + mk[q], weit, fu);
                    hs += br[scol(c + 31)] - own[h * 4 + q];
                }
            }
        }
        __syncthreads();
    }

    // ---- block reduce 128 -> 1 ----
    #pragma unroll
    for (int o = 16; o; o >>= 1) {
        fi += __shfl_down_sync(0xffffffffu, fi, o);
        fu += __shfl_down_sync(0xffffffffu, fu, o);
    }
    int wid = t >> 5;
    if (lane == 0) { s_i[wid] = fi; s_u[wid] = fu; }
    __syncthreads();
    if (wid == 0) {
        float ti = (lane < 4) ? s_i[lane] : 0.f;
        float tu = (lane < 4) ? s_u[lane] : 0.f;
        #pragma unroll
        for (int o = 2; o; o >>= 1) {
            ti += __shfl_down_sync(0xffffffffu, ti, o);
            tu += __shfl_down_sync(0xffffffffu, tu, o);
        }
        if (lane == 0) {
            g_part[(b * BANDS + band) * 2 + 0] = ti;
            g_part[(b * BANDS + band) * 2 + 1] = tu;
            __threadfence();
            unsigned int done = atomicAdd(&g_count, 1u);
            amLast = (done == NBLOCKS - 1);
        }
    }
    __syncthreads();

    // ---- last CTA: finalize ----
    if (amLast) {
        double w = 0.0;
        if (t < NB) {
            double it = 0.0, un = 0.0;
            #pragma unroll
            for (int p = 0; p < BANDS; ++p) {
                it += (double)g_part[(t * BANDS + p) * 2 + 0];
                un += (double)g_part[(t * BANDS + p) * 2 + 1];
            }
            w = 1.0 - (2.0 * it + 0.5) / (un + 0.5);
        }
        #pragma unroll
        for (int o = 16; o; o >>= 1) w += __shfl_down_sync(0xffffffffu, w, o);
        __shared__ double sh[2];
        if (t < 64 && (t & 31) == 0) sh[t >> 5] = w;
        __syncthreads();
        if (t == 0) {
            out[0] = (float)((sh[0] + sh[1]) / (double)NB);
            g_count = 0;   // reset for next graph replay
        }
    }
}

extern "C" void kernel_launch(void* const* d_in, const int* in_sizes, int n_in,
                              void* d_out, int out_size) {
    const float* pred = (const float*)d_in[0];
    const float* mask = (const float*)d_in[1];
    float* out = (float*)d_out;

    fused_kernel<<<dim3(BANDS, NB), NTH>>>(pred, mask, out);
}